// round 11
// baseline (speedup 1.0000x reference)
#include <cuda_runtime.h>
#include <cuda_fp16.h>
#include <math.h>
#include <stdint.h>

#define D 128
#define NMAX 100000
#define EMAX 800000
#define PMAX 100000
#define WELEM 16384

// ---------------- scratch (device globals; no allocation allowed) ----------
__device__ __align__(16) __half g_hA[NMAX * D];
__device__ __align__(16) __half g_hB[NMAX * D];   // holds half(x) for layer 0
__device__ __align__(16) __half g_hn[NMAX * D];
__device__ __align__(16) __half g_z[2 * PMAX * D];
__device__ __align__(16) __half g_z2[2 * PMAX * D];
__device__ __align__(16) float  g_acc[NMAX * D];  // fp32 accumulator (layer-0 split)
__device__ __align__(16) __half g_wc[8 * WELEM];  // weights: half, transposed [n][k]
__device__ int   g_deg[NMAX];
__device__ int   g_rowstart[NMAX];
__device__ int   g_cursor[NMAX];
__device__ int   g_csrsrc[EMAX];
__device__ int   g_bsum[256];
__device__ int   g_boff[256];

// ---------------- operand pre-conversion -----------------------------------
struct WPtrs { const float* p[8]; };

__global__ void convw_k(WPtrs w, __half* out) {
    int m = blockIdx.y;
    int i = blockIdx.x * 256 + threadIdx.x;
    if (i < WELEM) {
        int k = i >> 7, n = i & 127;
        out[m * WELEM + n * 128 + k] = __float2half_rn(w.p[m][i]);
    }
}

__global__ void convx_k(const float* __restrict__ in, __half* __restrict__ out, int n) {
    int i = blockIdx.x * 256 + threadIdx.x;
    if (i < n) out[i] = __float2half_rn(in[i]);
}

// ---------------- CSR build ------------------------------------------------
__global__ void zero_k(int n) {
    int i = blockIdx.x * blockDim.x + threadIdx.x;
    if (i < n) { g_deg[i] = 0; g_cursor[i] = 0; }
}

__global__ void hist_k(const int* __restrict__ dst, int E) {
    int e = blockIdx.x * blockDim.x + threadIdx.x;
    if (e < E) atomicAdd(&g_deg[dst[e]], 1);
}

__global__ void scan1_k(int n) {
    __shared__ int s[512];
    int tid = threadIdx.x;
    int i = blockIdx.x * 512 + tid;
    int v = (i < n) ? g_deg[i] : 0;
    s[tid] = v;
    __syncthreads();
    for (int off = 1; off < 512; off <<= 1) {
        int t = (tid >= off) ? s[tid - off] : 0;
        __syncthreads();
        s[tid] += t;
        __syncthreads();
    }
    if (i < n) g_rowstart[i] = s[tid] - v;
    if (tid == 511) g_bsum[blockIdx.x] = s[511];
}

__global__ void scan2_k(int nb) {
    __shared__ int s[256];
    int tid = threadIdx.x;
    int v = (tid < nb) ? g_bsum[tid] : 0;
    s[tid] = v;
    __syncthreads();
    for (int off = 1; off < 256; off <<= 1) {
        int t = (tid >= off) ? s[tid - off] : 0;
        __syncthreads();
        s[tid] += t;
        __syncthreads();
    }
    g_boff[tid] = s[tid] - v;
}

__global__ void scan3_k(int n) {
    int i = blockIdx.x * blockDim.x + threadIdx.x;
    if (i < n) g_rowstart[i] += g_boff[i >> 9];
}

__global__ void scatter_k(const int* __restrict__ src, const int* __restrict__ dst, int E) {
    int e = blockIdx.x * blockDim.x + threadIdx.x;
    if (e >= E) return;
    int d = dst[e];
    int p = atomicAdd(&g_cursor[d], 1);
    g_csrsrc[g_rowstart[d] + p] = src[e];
}

// ---------------- mean aggregation: 16 lanes/node, uint4 loads -------------
__global__ void agg_k(const __half* __restrict__ h, __half* __restrict__ hn, int n) {
    int t = blockIdx.x * blockDim.x + threadIdx.x;
    int node = t >> 4, l = t & 15;
    if (node >= n) return;
    int st = g_rowstart[node], d = g_deg[node];
    float a0 = 0.f, a1 = 0.f, a2 = 0.f, a3 = 0.f;
    float a4 = 0.f, a5 = 0.f, a6 = 0.f, a7 = 0.f;
    for (int j = 0; j < d; j++) {
        int s = g_csrsrc[st + j];
        uint4 u = *(const uint4*)(h + (size_t)s * D + l * 8);
        float2 p0 = __half22float2(*(__half2*)&u.x);
        float2 p1 = __half22float2(*(__half2*)&u.y);
        float2 p2 = __half22float2(*(__half2*)&u.z);
        float2 p3 = __half22float2(*(__half2*)&u.w);
        a0 += p0.x; a1 += p0.y; a2 += p1.x; a3 += p1.y;
        a4 += p2.x; a5 += p2.y; a6 += p3.x; a7 += p3.y;
    }
    float inv = 1.f / fmaxf((float)d, 1.f);
    __half2 o0 = __floats2half2_rn(a0 * inv, a1 * inv);
    __half2 o1 = __floats2half2_rn(a2 * inv, a3 * inv);
    __half2 o2 = __floats2half2_rn(a4 * inv, a5 * inv);
    __half2 o3 = __floats2half2_rn(a6 * inv, a7 * inv);
    uint4 o;
    o.x = *(uint32_t*)&o0; o.y = *(uint32_t*)&o1;
    o.z = *(uint32_t*)&o2; o.w = *(uint32_t*)&o3;
    *(uint4*)(hn + (size_t)node * D + l * 8) = o;
}

// ---------------- fp16 tensor-core GEMM: 128x64 tile, cp.async + ldmatrix --
// grid = (ceil(M/128), 2); blockIdx.y selects 64-col half.
// 8 warps 4x2: warp tile 32 rows x 32 cols; mt=2, nt=4; 32 fp32 accum/thread.
#define BK 64
#define SAB_S 36                  // words per 64-half row (128B data + 16B pad)
#define A_TILE_W (128 * SAB_S)    // 4608 words
#define B_TILE_W (64 * SAB_S)     // 2304 words
#define SLAB_W   (A_TILE_W + B_TILE_W)
#define GEMM_SMEM (2 * SLAB_W * 4)   // 55296 bytes

__device__ __forceinline__ void cp16(uint32_t dst, const void* src, bool pred) {
    int sz = pred ? 16 : 0;
    asm volatile("cp.async.cg.shared.global [%0], [%1], 16, %2;\n"
                 :: "r"(dst), "l"(src), "r"(sz));
}

__device__ __forceinline__ void ldsm4(uint32_t& r0, uint32_t& r1, uint32_t& r2,
                                      uint32_t& r3, uint32_t addr) {
    asm volatile("ldmatrix.sync.aligned.m8n8.x4.shared.b16 {%0,%1,%2,%3}, [%4];"
                 : "=r"(r0), "=r"(r1), "=r"(r2), "=r"(r3) : "r"(addr));
}

__global__ void __launch_bounds__(256, 3) gemm_tc_k(
    const __half* __restrict__ A, const __half* __restrict__ A2,
    const __half* __restrict__ W, const __half* __restrict__ W2,
    const float* __restrict__ bias, __half* __restrict__ C,
    int M, int doRelu,
    const float* __restrict__ accIn, float* __restrict__ accOut)
{
    extern __shared__ uint32_t smem[];
    int tid = threadIdx.x;
    int lane = tid & 31;
    int w = tid >> 5;
    int wr = w >> 1, wc = w & 1;
    int blockRow = blockIdx.x * 128;
    int colBlk = blockIdx.y * 64;       // global column offset of this block
    int lq = lane >> 2;
    int lr = lane & 3;

    uint32_t sbase = (uint32_t)__cvta_generic_to_shared(smem);

    int T = (A2 != nullptr) ? 4 : 2;

    // ldmatrix per-lane word offsets within tile
    int aRowOff0 = (wr * 32 + (lane & 7) + ((lane >> 3) & 1) * 8) * SAB_S
                 + (lane >> 4) * 4;
    int bRowOff0 = (wc * 32 + ((lane >> 4) & 1) * 8 + (lane & 7)) * SAB_S
                 + ((lane >> 3) & 1) * 4;

    float c[2][4][4];
#pragma unroll
    for (int mt = 0; mt < 2; mt++)
#pragma unroll
        for (int nt = 0; nt < 4; nt++)
#pragma unroll
            for (int i = 0; i < 4; i++) c[mt][nt][i] = 0.f;

    auto loadTile = [&](int t, int buf) {
        const __half* Ap = (t >> 1) ? A2 : A;
        const __half* Wp = (t >> 1) ? W2 : W;
        int kt = (t & 1) * BK;
        uint32_t dA = sbase + (uint32_t)buf * SLAB_W * 4;
        uint32_t dB = dA + A_TILE_W * 4;
        // A: 128 rows x 8 chunks of 16B = 1024 chunks, 4/thread
#pragma unroll
        for (int i = 0; i < 4; i++) {
            int q = tid + i * 256;
            int r = q >> 3, ch = q & 7;
            int grow = blockRow + r;
            cp16(dA + (uint32_t)(r * SAB_S + ch * 4) * 4,
                 Ap + (size_t)grow * D + kt + ch * 8, grow < M);
        }
        // B: 64 n-rows x 8 chunks of 16B = 512 chunks, 2/thread
#pragma unroll
        for (int i = 0; i < 2; i++) {
            int q = tid + i * 256;
            int r = q >> 3, ch = q & 7;
            cp16(dB + (uint32_t)(r * SAB_S + ch * 4) * 4,
                 Wp + (size_t)(colBlk + r) * D + kt + ch * 8, true);
        }
    };

    loadTile(0, 0);
    asm volatile("cp.async.commit_group;\n");

#pragma unroll 1
    for (int t = 0; t < 4; t++) {
        if (t >= T) break;
        int buf = t & 1;
        if (t + 1 < T) loadTile(t + 1, buf ^ 1);
        asm volatile("cp.async.commit_group;\n");
        asm volatile("cp.async.wait_group 1;\n");
        __syncthreads();

        uint32_t tAaddr = sbase + (uint32_t)(buf * SLAB_W) * 4;
        uint32_t tBaddr = tAaddr + A_TILE_W * 4;
#pragma unroll
        for (int ks = 0; ks < 4; ks++) {
            int kw = ks * 8;
            uint32_t a[2][4];
#pragma unroll
            for (int mt = 0; mt < 2; mt++)
                ldsm4(a[mt][0], a[mt][1], a[mt][2], a[mt][3],
                      tAaddr + (uint32_t)(aRowOff0 + mt * 16 * SAB_S + kw) * 4);
            uint32_t b[4][2];
#pragma unroll
            for (int j = 0; j < 2; j++)
                ldsm4(b[2 * j][0], b[2 * j][1], b[2 * j + 1][0], b[2 * j + 1][1],
                      tBaddr + (uint32_t)(bRowOff0 + j * 16 * SAB_S + kw) * 4);
#pragma unroll
            for (int mt = 0; mt < 2; mt++)
#pragma unroll
                for (int nt = 0; nt < 4; nt++) {
                    asm volatile(
                        "mma.sync.aligned.m16n8k16.row.col.f32.f16.f16.f32 "
                        "{%0,%1,%2,%3}, {%4,%5,%6,%7}, {%8,%9}, {%0,%1,%2,%3};"
                        : "+f"(c[mt][nt][0]), "+f"(c[mt][nt][1]),
                          "+f"(c[mt][nt][2]), "+f"(c[mt][nt][3])
                        : "r"(a[mt][0]), "r"(a[mt][1]), "r"(a[mt][2]), "r"(a[mt][3]),
                          "r"(b[nt][0]), "r"(b[nt][1]));
                }
        }
        __syncthreads();
    }

    // ---- epilogue ----
    if (accOut != nullptr) {
#pragma unroll
        for (int mt = 0; mt < 2; mt++) {
#pragma unroll
            for (int nt = 0; nt < 4; nt++) {
                int col = colBlk + wc * 32 + nt * 8 + lr * 2;
                int r0 = blockRow + wr * 32 + mt * 16 + lq;
                if (r0 < M)
                    *(float2*)(accOut + (size_t)r0 * D + col) =
                        make_float2(c[mt][nt][0], c[mt][nt][1]);
                int r1 = r0 + 8;
                if (r1 < M)
                    *(float2*)(accOut + (size_t)r1 * D + col) =
                        make_float2(c[mt][nt][2], c[mt][nt][3]);
            }
        }
        return;
    }
#pragma unroll
    for (int mt = 0; mt < 2; mt++) {
#pragma unroll
        for (int nt = 0; nt < 4; nt++) {
            int col = colBlk + wc * 32 + nt * 8 + lr * 2;
            float bias0 = bias[col], bias1 = bias[col + 1];
            int r0 = blockRow + wr * 32 + mt * 16 + lq;
            if (r0 < M) {
                float o0 = c[mt][nt][0] + bias0;
                float o1 = c[mt][nt][1] + bias1;
                if (accIn) {
                    float2 ac = *(const float2*)(accIn + (size_t)r0 * D + col);
                    o0 += ac.x; o1 += ac.y;
                }
                if (doRelu) { o0 = fmaxf(o0, 0.f); o1 = fmaxf(o1, 0.f); }
                __half2 h = __floats2half2_rn(o0, o1);
                *(uint32_t*)(C + (size_t)r0 * D + col) = *(uint32_t*)&h;
            }
            int r1 = r0 + 8;
            if (r1 < M) {
                float o2 = c[mt][nt][2] + bias0;
                float o3 = c[mt][nt][3] + bias1;
                if (accIn) {
                    float2 ac = *(const float2*)(accIn + (size_t)r1 * D + col);
                    o2 += ac.x; o3 += ac.y;
                }
                if (doRelu) { o2 = fmaxf(o2, 0.f); o3 = fmaxf(o3, 0.f); }
                __half2 h = __floats2half2_rn(o2, o3);
                *(uint32_t*)(C + (size_t)r1 * D + col) = *(uint32_t*)&h;
            }
        }
    }
}

// ---------------- predictor -------------------------------------------------
__global__ void buildz_k(const __half* __restrict__ h,
                         const int* __restrict__ ps, const int* __restrict__ pd,
                         const int* __restrict__ ns, const int* __restrict__ nd,
                         int P) {
    int t = blockIdx.x * blockDim.x + threadIdx.x;
    int row = t >> 4, l = t & 15;
    if (row >= 2 * P) return;
    int s, d;
    if (row < P) { s = ps[row]; d = pd[row]; }
    else         { s = ns[row - P]; d = nd[row - P]; }
    uint4 ua = *(const uint4*)(h + (size_t)s * D + l * 8);
    uint4 ub = *(const uint4*)(h + (size_t)d * D + l * 8);
    __half2 o0 = __hmul2(*(__half2*)&ua.x, *(__half2*)&ub.x);
    __half2 o1 = __hmul2(*(__half2*)&ua.y, *(__half2*)&ub.y);
    __half2 o2 = __hmul2(*(__half2*)&ua.z, *(__half2*)&ub.z);
    __half2 o3 = __hmul2(*(__half2*)&ua.w, *(__half2*)&ub.w);
    uint4 o;
    o.x = *(uint32_t*)&o0; o.y = *(uint32_t*)&o1;
    o.z = *(uint32_t*)&o2; o.w = *(uint32_t*)&o3;
    *(uint4*)(g_z + (size_t)row * D + l * 8) = o;
}

__global__ void final_k(const __half* __restrict__ z,
                        const float* __restrict__ Wp2, const float* __restrict__ bp2,
                        float* __restrict__ out, int P) {
    int t = blockIdx.x * blockDim.x + threadIdx.x;
    int row = t >> 5, lane = t & 31;
    if (row >= 2 * P) return;
    uint2 u = *(const uint2*)(z + (size_t)row * D + lane * 4);
    float2 p0 = __half22float2(*(__half2*)&u.x);
    float2 p1 = __half22float2(*(__half2*)&u.y);
    float vv[4] = {p0.x, p0.y, p1.x, p1.y};
    float d0 = 0.f, d1 = 0.f;
#pragma unroll
    for (int j = 0; j < 4; j++) {
        int k = lane * 4 + j;
        d0 += vv[j] * Wp2[k * 2 + 0];
        d1 += vv[j] * Wp2[k * 2 + 1];
    }
#pragma unroll
    for (int off = 16; off; off >>= 1) {
        d0 += __shfl_down_sync(0xffffffffu, d0, off);
        d1 += __shfl_down_sync(0xffffffffu, d1, off);
    }
    if (lane == 0) {
        float l0 = d0 + bp2[0], l1 = d1 + bp2[1];
        float m = fmaxf(l0, l1);
        float e0 = expf(l0 - m), e1 = expf(l1 - m);
        out[row] = e1 / (e0 + e1);
    }
}

// ---------------- launch ----------------------------------------------------
extern "C" void kernel_launch(void* const* d_in, const int* in_sizes, int n_in,
                              void* d_out, int out_size) {
    const float* x   = (const float*)d_in[0];
    const int* src   = (const int*)d_in[1];
    const int* dst   = (const int*)d_in[2];
    const int* ps    = (const int*)d_in[3];
    const int* pd    = (const int*)d_in[4];
    const int* ns    = (const int*)d_in[5];
    const int* nd    = (const int*)d_in[6];
    const float* Ws0 = (const float*)d_in[7];
    const float* Wn0 = (const float*)d_in[8];
    const float* b0  = (const float*)d_in[9];
    const float* Ws1 = (const float*)d_in[10];
    const float* Wn1 = (const float*)d_in[11];
    const float* b1  = (const float*)d_in[12];
    const float* Ws2 = (const float*)d_in[13];
    const float* Wn2 = (const float*)d_in[14];
    const float* b2  = (const float*)d_in[15];
    const float* Wp0 = (const float*)d_in[16];
    const float* bp0 = (const float*)d_in[17];
    const float* Wp1 = (const float*)d_in[18];
    const float* bp1 = (const float*)d_in[19];
    const float* Wp2 = (const float*)d_in[20];
    const float* bp2 = (const float*)d_in[21];

    int N = in_sizes[0] / D;
    int E = in_sizes[1];
    int P = in_sizes[3];
    float* out = (float*)d_out;

    __half *hA, *hB, *hn, *z, *z2, *wcb;
    float* acc;
    cudaGetSymbolAddress((void**)&hA, g_hA);
    cudaGetSymbolAddress((void**)&hB, g_hB);
    cudaGetSymbolAddress((void**)&hn, g_hn);
    cudaGetSymbolAddress((void**)&z,  g_z);
    cudaGetSymbolAddress((void**)&z2, g_z2);
    cudaGetSymbolAddress((void**)&wcb, g_wc);
    cudaGetSymbolAddress((void**)&acc, g_acc);

    cudaFuncSetAttribute(gemm_tc_k, cudaFuncAttributeMaxDynamicSharedMemorySize, GEMM_SMEM);

    const __half* wc0 = wcb;
    const __half* wc1 = wcb + 1 * WELEM;
    const __half* wc2 = wcb + 2 * WELEM;
    const __half* wc3 = wcb + 3 * WELEM;
    const __half* wc4 = wcb + 4 * WELEM;
    const __half* wc5 = wcb + 5 * WELEM;
    const __half* wc6 = wcb + 6 * WELEM;
    const __half* wc7 = wcb + 7 * WELEM;

    WPtrs wp;
    wp.p[0] = Ws0; wp.p[1] = Wn0; wp.p[2] = Ws1; wp.p[3] = Wn1;
    wp.p[4] = Ws2; wp.p[5] = Wn2; wp.p[6] = Wp0; wp.p[7] = Wp1;

    int nb = (N + 511) / 512;
    int aggBlocks  = (N * 16 + 255) / 256;
    dim3 gemmGridN((N + 127) / 128, 2);

    convw_k<<<dim3((WELEM + 255) / 256, 8), 256>>>(wp, wcb);       // 0
    convx_k<<<(N * D + 255) / 256, 256>>>(x, hB, N * D);           // 1
    zero_k<<<(N + 255) / 256, 256>>>(N);                           // 2
    // layer-0 self GEMM at slot 3 (profiled): acc = xc @ Ws0
    gemm_tc_k<<<gemmGridN, 256, GEMM_SMEM>>>(hB, nullptr, wc0, nullptr,
                                             b0, nullptr, N, 0,
                                             nullptr, acc);        // 3
    hist_k<<<(E + 255) / 256, 256>>>(dst, E);                      // 4
    scan1_k<<<nb, 512>>>(N);
    scan2_k<<<1, 256>>>(nb);
    scan3_k<<<(N + 255) / 256, 256>>>(N);
    scatter_k<<<(E + 255) / 256, 256>>>(src, dst, E);

    // layer 0 (neigh part): hA = relu(acc + agg(xc)@Wn0 + b0)
    agg_k<<<aggBlocks, 256>>>(hB, hn, N);
    gemm_tc_k<<<gemmGridN, 256, GEMM_SMEM>>>(hn, nullptr, wc1, nullptr,
                                             b0, hA, N, 1, acc, nullptr);
    // layer 1: hA -> hB (relu), dual
    agg_k<<<aggBlocks, 256>>>(hA, hn, N);
    gemm_tc_k<<<gemmGridN, 256, GEMM_SMEM>>>(hA, hn, wc2, wc3, b1, hB, N, 1,
                                             nullptr, nullptr);
    // layer 2: hB -> hA (no act), dual
    agg_k<<<aggBlocks, 256>>>(hB, hn, N);
    gemm_tc_k<<<gemmGridN, 256, GEMM_SMEM>>>(hB, hn, wc4, wc5, b2, hA, N, 0,
                                             nullptr, nullptr);

    // predictor
    int M2 = 2 * P;
    int zBlocks16 = (M2 * 16 + 255) / 256;
    int zBlocks32 = (M2 * 32 + 255) / 256;
    dim3 gemmGridP((M2 + 127) / 128, 2);
    buildz_k<<<zBlocks16, 256>>>(hA, ps, pd, ns, nd, P);
    gemm_tc_k<<<gemmGridP, 256, GEMM_SMEM>>>(z, nullptr, wc6, nullptr, bp0, z2,
                                             M2, 1, nullptr, nullptr);
    gemm_tc_k<<<gemmGridP, 256, GEMM_SMEM>>>(z2, nullptr, wc7, nullptr, bp1, z,
                                             M2, 1, nullptr, nullptr);
    final_k<<<zBlocks32, 256>>>(z, Wp2, bp2, out, P);
}

// round 12
// speedup vs baseline: 1.2552x; 1.2552x over previous
#include <cuda_runtime.h>
#include <cuda_fp16.h>
#include <math.h>
#include <stdint.h>

#define D 128
#define NMAX 100000
#define EMAX 800000
#define PMAX 100000
#define WELEM 16384

// ---------------- scratch (device globals; no allocation allowed) ----------
__device__ __align__(16) __half g_hA[NMAX * D];
__device__ __align__(16) __half g_hB[NMAX * D];   // holds half(x) for layer 0
__device__ __align__(16) __half g_hn[NMAX * D];
__device__ __align__(16) __half g_z[2 * PMAX * D];   // layer-0 self acc, then predictor z
__device__ __align__(16) __half g_z2[2 * PMAX * D];
__device__ __align__(16) __half g_wc[8 * WELEM];  // weights: half, transposed [n][k]
__device__ int   g_deg[NMAX];
__device__ int   g_rowstart[NMAX];
__device__ int   g_cursor[NMAX];
__device__ int   g_csrsrc[EMAX];
__device__ int   g_bsum[256];
__device__ int   g_boff[256];

// ---------------- operand pre-conversion -----------------------------------
struct WPtrs { const float* p[8]; };

__global__ void convw_k(WPtrs w, __half* out) {
    int m = blockIdx.y;
    int i = blockIdx.x * 256 + threadIdx.x;
    if (i < WELEM) {
        int k = i >> 7, n = i & 127;
        out[m * WELEM + n * 128 + k] = __float2half_rn(w.p[m][i]);
    }
}

__global__ void convx_k(const float* __restrict__ in, __half* __restrict__ out, int n) {
    int i = blockIdx.x * 256 + threadIdx.x;
    if (i < n) out[i] = __float2half_rn(in[i]);
}

// ---------------- CSR build ------------------------------------------------
__global__ void zero_k(int n) {
    int i = blockIdx.x * blockDim.x + threadIdx.x;
    if (i < n) { g_deg[i] = 0; g_cursor[i] = 0; }
}

__global__ void hist_k(const int* __restrict__ dst, int E) {
    int e = blockIdx.x * blockDim.x + threadIdx.x;
    if (e < E) atomicAdd(&g_deg[dst[e]], 1);
}

__global__ void scan1_k(int n) {
    __shared__ int s[512];
    int tid = threadIdx.x;
    int i = blockIdx.x * 512 + tid;
    int v = (i < n) ? g_deg[i] : 0;
    s[tid] = v;
    __syncthreads();
    for (int off = 1; off < 512; off <<= 1) {
        int t = (tid >= off) ? s[tid - off] : 0;
        __syncthreads();
        s[tid] += t;
        __syncthreads();
    }
    if (i < n) g_rowstart[i] = s[tid] - v;
    if (tid == 511) g_bsum[blockIdx.x] = s[511];
}

__global__ void scan2_k(int nb) {
    __shared__ int s[256];
    int tid = threadIdx.x;
    int v = (tid < nb) ? g_bsum[tid] : 0;
    s[tid] = v;
    __syncthreads();
    for (int off = 1; off < 256; off <<= 1) {
        int t = (tid >= off) ? s[tid - off] : 0;
        __syncthreads();
        s[tid] += t;
        __syncthreads();
    }
    g_boff[tid] = s[tid] - v;
}

__global__ void scan3_k(int n) {
    int i = blockIdx.x * blockDim.x + threadIdx.x;
    if (i < n) g_rowstart[i] += g_boff[i >> 9];
}

__global__ void scatter_k(const int* __restrict__ src, const int* __restrict__ dst, int E) {
    int e = blockIdx.x * blockDim.x + threadIdx.x;
    if (e >= E) return;
    int d = dst[e];
    int p = atomicAdd(&g_cursor[d], 1);
    g_csrsrc[g_rowstart[d] + p] = src[e];
}

// ---------------- mean aggregation: 16 lanes/node, uint4 loads -------------
__global__ void agg_k(const __half* __restrict__ h, __half* __restrict__ hn, int n) {
    int t = blockIdx.x * blockDim.x + threadIdx.x;
    int node = t >> 4, l = t & 15;
    if (node >= n) return;
    int st = g_rowstart[node], d = g_deg[node];
    float a0 = 0.f, a1 = 0.f, a2 = 0.f, a3 = 0.f;
    float a4 = 0.f, a5 = 0.f, a6 = 0.f, a7 = 0.f;
    for (int j = 0; j < d; j++) {
        int s = g_csrsrc[st + j];
        uint4 u = *(const uint4*)(h + (size_t)s * D + l * 8);
        float2 p0 = __half22float2(*(__half2*)&u.x);
        float2 p1 = __half22float2(*(__half2*)&u.y);
        float2 p2 = __half22float2(*(__half2*)&u.z);
        float2 p3 = __half22float2(*(__half2*)&u.w);
        a0 += p0.x; a1 += p0.y; a2 += p1.x; a3 += p1.y;
        a4 += p2.x; a5 += p2.y; a6 += p3.x; a7 += p3.y;
    }
    float inv = 1.f / fmaxf((float)d, 1.f);
    __half2 o0 = __floats2half2_rn(a0 * inv, a1 * inv);
    __half2 o1 = __floats2half2_rn(a2 * inv, a3 * inv);
    __half2 o2 = __floats2half2_rn(a4 * inv, a5 * inv);
    __half2 o3 = __floats2half2_rn(a6 * inv, a7 * inv);
    uint4 o;
    o.x = *(uint32_t*)&o0; o.y = *(uint32_t*)&o1;
    o.z = *(uint32_t*)&o2; o.w = *(uint32_t*)&o3;
    *(uint4*)(hn + (size_t)node * D + l * 8) = o;
}

// ---------------- fp16 tensor-core GEMM (round-9 core) ---------------------
// 128x128 tile, 8 warps 4x2 (warp 32x64), BK=64, cp.async 2-buffer, ldmatrix.
// Modes: normal C-out (bias optional, relu optional, accIn(half) optional);
//        probOut mode: fused z2@Wp1+bp1 -> relu -> @Wp2+bp2 -> softmax[:,1].
#define BK 64
#define SAB_S 36
#define TILE_W (128 * SAB_S)
#define GEMM_SMEM (4 * TILE_W * 4)   // 73728

__device__ __forceinline__ void cp16(uint32_t dst, const void* src, bool pred) {
    int sz = pred ? 16 : 0;
    asm volatile("cp.async.cg.shared.global [%0], [%1], 16, %2;\n"
                 :: "r"(dst), "l"(src), "r"(sz));
}

__device__ __forceinline__ void ldsm4(uint32_t& r0, uint32_t& r1, uint32_t& r2,
                                      uint32_t& r3, uint32_t addr) {
    asm volatile("ldmatrix.sync.aligned.m8n8.x4.shared.b16 {%0,%1,%2,%3}, [%4];"
                 : "=r"(r0), "=r"(r1), "=r"(r2), "=r"(r3) : "r"(addr));
}

__global__ void __launch_bounds__(256) gemm_tc_k(
    const __half* __restrict__ A, const __half* __restrict__ A2,
    const __half* __restrict__ W, const __half* __restrict__ W2,
    const float* __restrict__ bias, __half* __restrict__ C,
    int M, int doRelu,
    const __half* __restrict__ accIn,
    float* __restrict__ probOut,
    const float* __restrict__ Wp2, const float* __restrict__ bp2)
{
    extern __shared__ uint32_t smem[];
    int tid = threadIdx.x;
    int lane = tid & 31;
    int w = tid >> 5;
    int wr = w >> 1, wc = w & 1;
    int blockRow = blockIdx.x * 128;
    int lq = lane >> 2;
    int lr = lane & 3;

    uint32_t sbase = (uint32_t)__cvta_generic_to_shared(smem);

    int T = (A2 != nullptr) ? 4 : 2;

    int aRowOff0 = (wr * 32 + (lane & 7) + ((lane >> 3) & 1) * 8) * SAB_S
                 + (lane >> 4) * 4;
    int bRowOff0 = (wc * 64 + ((lane >> 4) & 1) * 8 + (lane & 7)) * SAB_S
                 + ((lane >> 3) & 1) * 4;

    float c[2][8][4];
#pragma unroll
    for (int mt = 0; mt < 2; mt++)
#pragma unroll
        for (int nt = 0; nt < 8; nt++)
#pragma unroll
            for (int i = 0; i < 4; i++) c[mt][nt][i] = 0.f;

    auto loadTile = [&](int t, int buf) {
        const __half* Ap = (t >> 1) ? A2 : A;
        const __half* Wp = (t >> 1) ? W2 : W;
        int kt = (t & 1) * BK;
        uint32_t dA = sbase + (uint32_t)buf * 2 * TILE_W * 4;
        uint32_t dB = dA + TILE_W * 4;
#pragma unroll
        for (int i = 0; i < 4; i++) {
            int q = tid + i * 256;
            int r = q >> 3, ch = q & 7;
            int grow = blockRow + r;
            cp16(dA + (uint32_t)(r * SAB_S + ch * 4) * 4,
                 Ap + (size_t)grow * D + kt + ch * 8, grow < M);
        }
#pragma unroll
        for (int i = 0; i < 4; i++) {
            int q = tid + i * 256;
            int r = q >> 3, ch = q & 7;
            cp16(dB + (uint32_t)(r * SAB_S + ch * 4) * 4,
                 Wp + (size_t)r * D + kt + ch * 8, true);
        }
    };

    loadTile(0, 0);
    asm volatile("cp.async.commit_group;\n");

#pragma unroll 1
    for (int t = 0; t < 4; t++) {
        if (t >= T) break;
        int buf = t & 1;
        if (t + 1 < T) loadTile(t + 1, buf ^ 1);
        asm volatile("cp.async.commit_group;\n");
        asm volatile("cp.async.wait_group 1;\n");
        __syncthreads();

        uint32_t tAaddr = sbase + (uint32_t)(buf * 2 * TILE_W) * 4;
        uint32_t tBaddr = tAaddr + TILE_W * 4;
#pragma unroll
        for (int ks = 0; ks < 4; ks++) {
            int kw = ks * 8;
            uint32_t a[2][4];
#pragma unroll
            for (int mt = 0; mt < 2; mt++)
                ldsm4(a[mt][0], a[mt][1], a[mt][2], a[mt][3],
                      tAaddr + (uint32_t)(aRowOff0 + mt * 16 * SAB_S + kw) * 4);
            uint32_t b[8][2];
#pragma unroll
            for (int j = 0; j < 4; j++)
                ldsm4(b[2 * j][0], b[2 * j][1], b[2 * j + 1][0], b[2 * j + 1][1],
                      tBaddr + (uint32_t)(bRowOff0 + j * 16 * SAB_S + kw) * 4);
#pragma unroll
            for (int mt = 0; mt < 2; mt++)
#pragma unroll
                for (int nt = 0; nt < 8; nt++) {
                    asm volatile(
                        "mma.sync.aligned.m16n8k16.row.col.f32.f16.f16.f32 "
                        "{%0,%1,%2,%3}, {%4,%5,%6,%7}, {%8,%9}, {%0,%1,%2,%3};"
                        : "+f"(c[mt][nt][0]), "+f"(c[mt][nt][1]),
                          "+f"(c[mt][nt][2]), "+f"(c[mt][nt][3])
                        : "r"(a[mt][0]), "r"(a[mt][1]), "r"(a[mt][2]), "r"(a[mt][3]),
                          "r"(b[nt][0]), "r"(b[nt][1]));
                }
        }
        __syncthreads();
    }

    // ======== probOut mode: fused bias+relu+Wp2 dot+softmax ========
    if (probOut != nullptr) {
        float d0[4] = {0.f, 0.f, 0.f, 0.f};
        float d1[4] = {0.f, 0.f, 0.f, 0.f};
#pragma unroll
        for (int mt = 0; mt < 2; mt++) {
#pragma unroll
            for (int nt = 0; nt < 8; nt++) {
                int col = wc * 64 + nt * 8 + lr * 2;
                float bias0 = bias[col], bias1 = bias[col + 1];
                float w20 = Wp2[col * 2 + 0],       w21 = Wp2[col * 2 + 1];
                float w30 = Wp2[(col + 1) * 2 + 0], w31 = Wp2[(col + 1) * 2 + 1];
                float v0 = fmaxf(c[mt][nt][0] + bias0, 0.f);
                float v1 = fmaxf(c[mt][nt][1] + bias1, 0.f);
                float v2 = fmaxf(c[mt][nt][2] + bias0, 0.f);
                float v3 = fmaxf(c[mt][nt][3] + bias1, 0.f);
                d0[mt * 2 + 0] += v0 * w20 + v1 * w30;
                d1[mt * 2 + 0] += v0 * w21 + v1 * w31;
                d0[mt * 2 + 1] += v2 * w20 + v3 * w30;
                d1[mt * 2 + 1] += v2 * w21 + v3 * w31;
            }
        }
        // reduce over lr group (lanes lq*4 + lr, lr = 0..3)
#pragma unroll
        for (int s = 0; s < 4; s++) {
            d0[s] += __shfl_xor_sync(0xffffffffu, d0[s], 1);
            d0[s] += __shfl_xor_sync(0xffffffffu, d0[s], 2);
            d1[s] += __shfl_xor_sync(0xffffffffu, d1[s], 1);
            d1[s] += __shfl_xor_sync(0xffffffffu, d1[s], 2);
        }
        float* sred = (float*)smem;   // [2][128][2] = 512 floats
        if (lr == 0) {
#pragma unroll
            for (int s = 0; s < 4; s++) {
                int mt = s >> 1, half = s & 1;
                int rowL = wr * 32 + mt * 16 + half * 8 + lq;
                sred[wc * 256 + rowL * 2 + 0] = d0[s];
                sred[wc * 256 + rowL * 2 + 1] = d1[s];
            }
        }
        __syncthreads();
        if (tid < 128) {
            int grow = blockRow + tid;
            if (grow < M) {
                float D0 = sred[tid * 2 + 0] + sred[256 + tid * 2 + 0] + bp2[0];
                float D1 = sred[tid * 2 + 1] + sred[256 + tid * 2 + 1] + bp2[1];
                float mx = fmaxf(D0, D1);
                float e0 = expf(D0 - mx), e1 = expf(D1 - mx);
                probOut[grow] = e1 / (e0 + e1);
            }
        }
        return;
    }

    // ======== normal epilogue: [bias] + [accIn(half)] + [relu] -> half C ====
#pragma unroll
    for (int mt = 0; mt < 2; mt++) {
#pragma unroll
        for (int nt = 0; nt < 8; nt++) {
            int col = wc * 64 + nt * 8 + lr * 2;
            float bias0 = bias ? bias[col] : 0.f;
            float bias1 = bias ? bias[col + 1] : 0.f;
            int r0 = blockRow + wr * 32 + mt * 16 + lq;
            if (r0 < M) {
                float o0 = c[mt][nt][0] + bias0;
                float o1 = c[mt][nt][1] + bias1;
                if (accIn) {
                    uint32_t av = *(const uint32_t*)(accIn + (size_t)r0 * D + col);
                    float2 q = __half22float2(*(__half2*)&av);
                    o0 += q.x; o1 += q.y;
                }
                if (doRelu) { o0 = fmaxf(o0, 0.f); o1 = fmaxf(o1, 0.f); }
                __half2 h = __floats2half2_rn(o0, o1);
                *(uint32_t*)(C + (size_t)r0 * D + col) = *(uint32_t*)&h;
            }
            int r1 = r0 + 8;
            if (r1 < M) {
                float o2 = c[mt][nt][2] + bias0;
                float o3 = c[mt][nt][3] + bias1;
                if (accIn) {
                    uint32_t av = *(const uint32_t*)(accIn + (size_t)r1 * D + col);
                    float2 q = __half22float2(*(__half2*)&av);
                    o2 += q.x; o3 += q.y;
                }
                if (doRelu) { o2 = fmaxf(o2, 0.f); o3 = fmaxf(o3, 0.f); }
                __half2 h = __floats2half2_rn(o2, o3);
                *(uint32_t*)(C + (size_t)r1 * D + col) = *(uint32_t*)&h;
            }
        }
    }
}

// ---------------- predictor -------------------------------------------------
__global__ void buildz_k(const __half* __restrict__ h,
                         const int* __restrict__ ps, const int* __restrict__ pd,
                         const int* __restrict__ ns, const int* __restrict__ nd,
                         int P) {
    int t = blockIdx.x * blockDim.x + threadIdx.x;
    int row = t >> 4, l = t & 15;
    if (row >= 2 * P) return;
    int s, d;
    if (row < P) { s = ps[row]; d = pd[row]; }
    else         { s = ns[row - P]; d = nd[row - P]; }
    uint4 ua = *(const uint4*)(h + (size_t)s * D + l * 8);
    uint4 ub = *(const uint4*)(h + (size_t)d * D + l * 8);
    __half2 o0 = __hmul2(*(__half2*)&ua.x, *(__half2*)&ub.x);
    __half2 o1 = __hmul2(*(__half2*)&ua.y, *(__half2*)&ub.y);
    __half2 o2 = __hmul2(*(__half2*)&ua.z, *(__half2*)&ub.z);
    __half2 o3 = __hmul2(*(__half2*)&ua.w, *(__half2*)&ub.w);
    uint4 o;
    o.x = *(uint32_t*)&o0; o.y = *(uint32_t*)&o1;
    o.z = *(uint32_t*)&o2; o.w = *(uint32_t*)&o3;
    *(uint4*)(g_z + (size_t)row * D + l * 8) = o;
}

// ---------------- launch ----------------------------------------------------
extern "C" void kernel_launch(void* const* d_in, const int* in_sizes, int n_in,
                              void* d_out, int out_size) {
    const float* x   = (const float*)d_in[0];
    const int* src   = (const int*)d_in[1];
    const int* dst   = (const int*)d_in[2];
    const int* ps    = (const int*)d_in[3];
    const int* pd    = (const int*)d_in[4];
    const int* ns    = (const int*)d_in[5];
    const int* nd    = (const int*)d_in[6];
    const float* Ws0 = (const float*)d_in[7];
    const float* Wn0 = (const float*)d_in[8];
    const float* b0  = (const float*)d_in[9];
    const float* Ws1 = (const float*)d_in[10];
    const float* Wn1 = (const float*)d_in[11];
    const float* b1  = (const float*)d_in[12];
    const float* Ws2 = (const float*)d_in[13];
    const float* Wn2 = (const float*)d_in[14];
    const float* b2  = (const float*)d_in[15];
    const float* Wp0 = (const float*)d_in[16];
    const float* bp0 = (const float*)d_in[17];
    const float* Wp1 = (const float*)d_in[18];
    const float* bp1 = (const float*)d_in[19];
    const float* Wp2 = (const float*)d_in[20];
    const float* bp2 = (const float*)d_in[21];

    int N = in_sizes[0] / D;
    int E = in_sizes[1];
    int P = in_sizes[3];
    float* out = (float*)d_out;

    __half *hA, *hB, *hn, *z, *z2, *wcb;
    cudaGetSymbolAddress((void**)&hA, g_hA);
    cudaGetSymbolAddress((void**)&hB, g_hB);
    cudaGetSymbolAddress((void**)&hn, g_hn);
    cudaGetSymbolAddress((void**)&z,  g_z);
    cudaGetSymbolAddress((void**)&z2, g_z2);
    cudaGetSymbolAddress((void**)&wcb, g_wc);

    cudaFuncSetAttribute(gemm_tc_k, cudaFuncAttributeMaxDynamicSharedMemorySize, GEMM_SMEM);

    const __half* wc0 = wcb;
    const __half* wc1 = wcb + 1 * WELEM;
    const __half* wc2 = wcb + 2 * WELEM;
    const __half* wc3 = wcb + 3 * WELEM;
    const __half* wc4 = wcb + 4 * WELEM;
    const __half* wc5 = wcb + 5 * WELEM;
    const __half* wc6 = wcb + 6 * WELEM;
    const __half* wc7 = wcb + 7 * WELEM;

    WPtrs wp;
    wp.p[0] = Ws0; wp.p[1] = Wn0; wp.p[2] = Ws1; wp.p[3] = Wn1;
    wp.p[4] = Ws2; wp.p[5] = Wn2; wp.p[6] = Wp0; wp.p[7] = Wp1;

    int nb = (N + 511) / 512;
    int aggBlocks  = (N * 16 + 255) / 256;
    int gemmBlocksN = (N + 127) / 128;

    convw_k<<<dim3((WELEM + 255) / 256, 8), 256>>>(wp, wcb);       // 0
    convx_k<<<(N * D + 255) / 256, 256>>>(x, hB, N * D);           // 1
    zero_k<<<(N + 255) / 256, 256>>>(N);                           // 2
    // layer-0 self GEMM at slot 3 (profiled): z(half) = xc @ Ws0 (no bias)
    gemm_tc_k<<<gemmBlocksN, 256, GEMM_SMEM>>>(hB, nullptr, wc0, nullptr,
                                               nullptr, z, N, 0,
                                               nullptr, nullptr, nullptr, nullptr); // 3
    hist_k<<<(E + 255) / 256, 256>>>(dst, E);                      // 4
    scan1_k<<<nb, 512>>>(N);
    scan2_k<<<1, 256>>>(nb);
    scan3_k<<<(N + 255) / 256, 256>>>(N);
    scatter_k<<<(E + 255) / 256, 256>>>(src, dst, E);

    // layer 0 neigh: hA = relu(z + agg(xc)@Wn0 + b0)
    agg_k<<<aggBlocks, 256>>>(hB, hn, N);
    gemm_tc_k<<<gemmBlocksN, 256, GEMM_SMEM>>>(hn, nullptr, wc1, nullptr,
                                               b0, hA, N, 1,
                                               z, nullptr, nullptr, nullptr);
    // layer 1: hA -> hB (relu), dual
    agg_k<<<aggBlocks, 256>>>(hA, hn, N);
    gemm_tc_k<<<gemmBlocksN, 256, GEMM_SMEM>>>(hA, hn, wc2, wc3, b1, hB, N, 1,
                                               nullptr, nullptr, nullptr, nullptr);
    // layer 2: hB -> hA (no act), dual
    agg_k<<<aggBlocks, 256>>>(hB, hn, N);
    gemm_tc_k<<<gemmBlocksN, 256, GEMM_SMEM>>>(hB, hn, wc4, wc5, b2, hA, N, 0,
                                               nullptr, nullptr, nullptr, nullptr);

    // predictor
    int M2 = 2 * P;
    int zBlocks16 = (M2 * 16 + 255) / 256;
    int gemmBlocksP = (M2 + 127) / 128;
    buildz_k<<<zBlocks16, 256>>>(hA, ps, pd, ns, nd, P);
    // G1: z2 = relu(z @ Wp0 + bp0)
    gemm_tc_k<<<gemmBlocksP, 256, GEMM_SMEM>>>(z, nullptr, wc6, nullptr, bp0, z2,
                                               M2, 1, nullptr, nullptr, nullptr, nullptr);
    // G2 fused: out = softmax(relu(z2 @ Wp1 + bp1) @ Wp2 + bp2)[:,1]
    gemm_tc_k<<<gemmBlocksP, 256, GEMM_SMEM>>>(z2, nullptr, wc7, nullptr, bp1, nullptr,
                                               M2, 1, nullptr, out, Wp2, bp2);
}